// round 14
// baseline (speedup 1.0000x reference)
#include <cuda_runtime.h>
#include <cstdint>

#define BATCH 256
#define VOCAB 128000
#define RANK  64
#define ALPHA 0.4f
#define EPSF  1.1920928955078125e-07f   // np.finfo(float32).eps

#define KC1   256                // k-chunk per gemm1 block
#define NKC1  (VOCAB / KC1)      // 500 k-chunks
#define PART_SZ (128 * RANK)     // 8192 floats per partial

// ---------------- scratch (no allocations allowed) ----------------
__device__ float        g_Tpart[2 * NKC1 * PART_SZ];  // per-block partial T (33 MB)
__device__ float        g_T[BATCH * RANK];            // reduced T = L @ W
__device__ unsigned int g_maxL;                       // float bits of max|L|
__device__ unsigned int g_maxLp;                      // float bits of max|Lp_raw|

// ---------------- PTX helpers ----------------
typedef unsigned long long u64;

__device__ __forceinline__ unsigned smem_u32(const void* p) {
    unsigned a;
    asm("{ .reg .u64 t; cvta.to.shared.u64 t, %1; cvt.u32.u64 %0, t; }"
        : "=r"(a) : "l"(p));
    return a;
}
__device__ __forceinline__ void sts_b64(unsigned a, u64 v) {
    asm volatile("st.shared.b64 [%0], %1;" :: "r"(a), "l"(v));
}

// ldmatrix (sm_75+, valid on compute_103)
__device__ __forceinline__ void ldm_x4(unsigned addr, unsigned* r) {
    asm volatile("ldmatrix.sync.aligned.m8n8.x4.shared.b16 {%0,%1,%2,%3}, [%4];"
                 : "=r"(r[0]), "=r"(r[1]), "=r"(r[2]), "=r"(r[3]) : "r"(addr));
}
__device__ __forceinline__ void ldm_x4t(unsigned addr, unsigned* r) {
    asm volatile("ldmatrix.sync.aligned.m8n8.x4.trans.shared.b16 {%0,%1,%2,%3}, [%4];"
                 : "=r"(r[0]), "=r"(r[1]), "=r"(r[2]), "=r"(r[3]) : "r"(addr));
}
__device__ __forceinline__ void ldm_x2(unsigned addr, unsigned* r) {
    asm volatile("ldmatrix.sync.aligned.m8n8.x2.shared.b16 {%0,%1}, [%2];"
                 : "=r"(r[0]), "=r"(r[1]) : "r"(addr));
}
// bf16 mma (sm_80+, valid on compute_103)
__device__ __forceinline__ void mma_bf16(float* c, const unsigned* a, const unsigned* b) {
    asm volatile(
        "mma.sync.aligned.m16n8k16.row.col.f32.bf16.bf16.f32 "
        "{%0,%1,%2,%3}, {%4,%5,%6,%7}, {%8,%9}, {%0,%1,%2,%3};"
        : "+f"(c[0]), "+f"(c[1]), "+f"(c[2]), "+f"(c[3])
        : "r"(a[0]), "r"(a[1]), "r"(a[2]), "r"(a[3]), "r"(b[0]), "r"(b[1]));
}

// fp32 -> (hi,lo) bf16 split of a float4; each u64 = 4 packed bf16 in element order
__device__ __forceinline__ void split4(float4 v, u64& hi, u64& lo) {
    unsigned h01, h23, l01, l23;
    asm("cvt.rn.bf16x2.f32 %0, %1, %2;" : "=r"(h01) : "f"(v.y), "f"(v.x));
    asm("cvt.rn.bf16x2.f32 %0, %1, %2;" : "=r"(h23) : "f"(v.w), "f"(v.z));
    float hx = __uint_as_float(h01 << 16);
    float hy = __uint_as_float(h01 & 0xffff0000u);
    float hz = __uint_as_float(h23 << 16);
    float hw = __uint_as_float(h23 & 0xffff0000u);
    asm("cvt.rn.bf16x2.f32 %0, %1, %2;" : "=r"(l01) : "f"(v.y - hy), "f"(v.x - hx));
    asm("cvt.rn.bf16x2.f32 %0, %1, %2;" : "=r"(l23) : "f"(v.w - hw), "f"(v.z - hz));
    hi = (u64)h01 | ((u64)h23 << 32);
    lo = (u64)l01 | ((u64)l23 << 32);
}

// ---------------- K0: init g_T + maxima ----------------
__global__ void k_init() {
    int i = blockIdx.x * blockDim.x + threadIdx.x;
    if (i < BATCH * RANK) g_T[i] = 0.0f;
    if (i == 0) { g_maxL = 0u; g_maxLp = 0u; }
}

// ---------------- K1: partial T = L@W via split-bf16 mma.sync, fused max|L| ----------
// grid = (NKC1, 2 batch-halves), 256 threads (8 warps). Block tile 128 b x 64 r x 256 k.
// Register-prefetch pipeline: chunk k+1's LDGs issued before chunk k's MMA.
#define G1_LHI 0
#define G1_LLO 16384
#define G1_WHI 32768
#define G1_WLO 40960
#define G1_TOTAL 49152

__global__ __launch_bounds__(256, 2) void k_gemm1(const float* __restrict__ L,
                                                  const float* __restrict__ W) {
    extern __shared__ char sm1[];
    const unsigned sb = smem_u32(sm1);
    __shared__ float wred[8];

    const int tid  = threadIdx.x;
    const int wid  = tid >> 5;
    const int lane = tid & 31;
    const int k0blk = blockIdx.x * KC1;
    const int b0    = blockIdx.y * 128;

    // per-thread staging coords (fixed across chunks)
    const int lrow = tid >> 4;            // L row (two rows per thread via it)
    const int lkq  = tid & 15;
    const int wrow = tid >> 4;
    const int wrq  = tid & 15;

    float acc[8][4];
#pragma unroll
    for (int nt = 0; nt < 8; nt++)
#pragma unroll
        for (int q = 0; q < 4; q++) acc[nt][q] = 0.0f;

    float maxl = 0.0f;

    float4 lreg[8];
    float4 wreg[4];

    // prologue: load chunk 0
#pragma unroll
    for (int it = 0; it < 8; it++) {
        int row = (tid + it * 256) >> 4;
        int kq  = (tid + it * 256) & 15;
        lreg[it] = *(const float4*)(L + (size_t)(b0 + row) * VOCAB + k0blk + kq * 4);
    }
#pragma unroll
    for (int it = 0; it < 4; it++) {
        int krow = (tid + it * 256) >> 4;
        int rq   = (tid + it * 256) & 15;
        wreg[it] = *(const float4*)(W + (size_t)(k0blk + krow) * RANK + rq * 4);
    }

    for (int kt = 0; kt < KC1; kt += 64) {
        __syncthreads();            // previous MMA done reading smem
        // stage current regs -> smem (split to hi/lo), fused abs-max
#pragma unroll
        for (int it = 0; it < 8; it++) {
            int row = (tid + it * 256) >> 4;
            int kq  = (tid + it * 256) & 15;
            float4 v = lreg[it];
            maxl = fmaxf(maxl, fmaxf(fmaxf(fabsf(v.x), fabsf(v.y)),
                                     fmaxf(fabsf(v.z), fabsf(v.w))));
            unsigned soff = row * 128 + (((kq >> 1) ^ (row & 7)) << 4) + ((kq & 1) << 3);
            u64 hi, lo; split4(v, hi, lo);
            sts_b64(sb + G1_LHI + soff, hi);
            sts_b64(sb + G1_LLO + soff, lo);
        }
#pragma unroll
        for (int it = 0; it < 4; it++) {
            int krow = (tid + it * 256) >> 4;
            int rq   = (tid + it * 256) & 15;
            float4 v = wreg[it];
            unsigned soff = krow * 128 + (((rq >> 1) ^ (krow & 7)) << 4) + ((rq & 1) << 3);
            u64 hi, lo; split4(v, hi, lo);
            sts_b64(sb + G1_WHI + soff, hi);
            sts_b64(sb + G1_WLO + soff, lo);
        }
        __syncthreads();

        // prefetch next chunk (overlaps with MMA below)
        if (kt + 64 < KC1) {
            const int kn = k0blk + kt + 64;
#pragma unroll
            for (int it = 0; it < 8; it++) {
                int row = (tid + it * 256) >> 4;
                int kq  = (tid + it * 256) & 15;
                lreg[it] = *(const float4*)(L + (size_t)(b0 + row) * VOCAB + kn + kq * 4);
            }
#pragma unroll
            for (int it = 0; it < 4; it++) {
                int krow = (tid + it * 256) >> 4;
                int rq   = (tid + it * 256) & 15;
                wreg[it] = *(const float4*)(W + (size_t)(kn + krow) * RANK + rq * 4);
            }
        }

        // MMA on staged chunk
#pragma unroll
        for (int ks = 0; ks < 4; ks++) {
            const int arow = wid * 16 + (lane & 15);
            const unsigned aaddr = sb + arow * 128 +
                (((ks * 2 + (lane >> 4)) ^ (arow & 7)) << 4);
            const int kloc = ks * 16 + (lane & 15);
            unsigned ahi[4], alo[4];
            unsigned bhi[4][4];
#pragma unroll
            for (int nt2 = 0; nt2 < 4; nt2++) {
                unsigned baddr = sb + kloc * 128 +
                    (((nt2 * 2 + (lane >> 4)) ^ (lane & 7)) << 4);
                ldm_x4t(baddr + G1_WHI, bhi[nt2]);
            }
            ldm_x4(aaddr + G1_LHI, ahi);
#pragma unroll
            for (int nt2 = 0; nt2 < 4; nt2++) {
                mma_bf16(acc[nt2 * 2 + 0], ahi, bhi[nt2] + 0);
                mma_bf16(acc[nt2 * 2 + 1], ahi, bhi[nt2] + 2);
            }
#pragma unroll
            for (int nt2 = 0; nt2 < 4; nt2++) {
                unsigned blo[4];
                unsigned baddr = sb + kloc * 128 +
                    (((nt2 * 2 + (lane >> 4)) ^ (lane & 7)) << 4);
                ldm_x4t(baddr + G1_WLO, blo);
                mma_bf16(acc[nt2 * 2 + 0], ahi, blo + 0);
                mma_bf16(acc[nt2 * 2 + 1], ahi, blo + 2);
            }
            ldm_x4(aaddr + G1_LLO, alo);
#pragma unroll
            for (int nt2 = 0; nt2 < 4; nt2++) {
                mma_bf16(acc[nt2 * 2 + 0], alo, bhi[nt2] + 0);
                mma_bf16(acc[nt2 * 2 + 1], alo, bhi[nt2] + 2);
            }
        }
    }

    {
        float* dst = g_Tpart + (size_t)(blockIdx.y * NKC1 + blockIdx.x) * PART_SZ;
        const int r0 = (lane & 3) * 2;
        const int rowA = wid * 16 + (lane >> 2);
#pragma unroll
        for (int nt = 0; nt < 8; nt++) {
            int c = nt * 8 + r0;
            *(float2*)(dst + rowA * RANK + c)       = make_float2(acc[nt][0], acc[nt][1]);
            *(float2*)(dst + (rowA + 8) * RANK + c) = make_float2(acc[nt][2], acc[nt][3]);
        }
    }

#pragma unroll
    for (int off = 16; off > 0; off >>= 1)
        maxl = fmaxf(maxl, __shfl_xor_sync(0xffffffffu, maxl, off));
    if (lane == 0) wred[wid] = maxl;
    __syncthreads();
    if (tid == 0) {
        float m = wred[0];
#pragma unroll
        for (int k = 1; k < 8; k++) m = fmaxf(m, wred[k]);
        atomicMax(&g_maxL, __float_as_uint(m));
    }
}

// ---------------- K1b: reduce partials -> g_T ----------------
#define KGRP 10
#define KPER (NKC1 / KGRP)       // 50
__global__ void k_red() {
    const int i = blockIdx.x * blockDim.x + threadIdx.x;
    const int b = i >> 6;
    const int r = i & 63;
    const int half = b >> 7;
    const size_t off = (size_t)(b & 127) * RANK + r;
    const size_t base = ((size_t)half * NKC1 + blockIdx.y * KPER) * PART_SZ + off;

    float s0 = 0.f, s1 = 0.f;
#pragma unroll 2
    for (int p = 0; p < KPER; p += 2) {
        s0 += g_Tpart[base + (size_t)(p + 0) * PART_SZ];
        s1 += g_Tpart[base + (size_t)(p + 1) * PART_SZ];
    }
    atomicAdd(&g_T[i], s0 + s1);
}

// ---------------- K2: two-pass split-bf16 mma.sync over D = T@W.T ----------------
// Pass A (WRITE=false): maxLp = max|D - L|, no stores.
// Pass B (WRITE=true):  out   = c2*D + (alpha - c2)*L.
// grid = (VOCAB/128, BATCH/128), 256 threads (8 warps, 2M x 4N).
// mt-outer accumulation: acc = 16 regs -> 3 CTAs/SM; epilogue per mt overlaps
// the next mt's MMA.
#define SM2_TILE 16384
#define SM2_THI  0
#define SM2_TLO  (1 * SM2_TILE)
#define SM2_WHI  (2 * SM2_TILE)
#define SM2_WLO  (3 * SM2_TILE)
#define SM2_TOTAL (4 * SM2_TILE)      // 65536 B

__device__ __forceinline__ unsigned sw_addr(unsigned base, int row, int chunk) {
    return base + row * 128 + ((chunk ^ (row & 7)) << 4);
}

template <bool WRITE>
__global__ __launch_bounds__(256, 3) void k_pass(const float* __restrict__ L,
                                                 const float* __restrict__ W,
                                                 float* __restrict__ out) {
    extern __shared__ char sm2[];
    const unsigned sb = smem_u32(sm2);
    __shared__ float wred2[8];

    const int tid  = threadIdx.x;
    const int wid  = tid >> 5;
    const int lane = tid & 31;
    const int wm   = wid >> 2;
    const int wn   = wid & 3;
    const int j0   = blockIdx.x * 128;
    const int b0   = blockIdx.y * 128;

#pragma unroll
    for (int it = 0; it < 8; it++) {
        int idx = tid + it * 256;
        int row = idx >> 4;
        int rq  = idx & 15;
        unsigned soff = row * 128 + (((rq >> 1) ^ (row & 7)) << 4) + ((rq & 1) << 3);
        {
            float4 v = *(const float4*)(g_T + (size_t)(b0 + row) * RANK + rq * 4);
            u64 hi, lo; split4(v, hi, lo);
            sts_b64(sb + SM2_THI + soff, hi);
            sts_b64(sb + SM2_TLO + soff, lo);
        }
        {
            float4 v = *(const float4*)(W + (size_t)(j0 + row) * RANK + rq * 4);
            u64 hi, lo; split4(v, hi, lo);
            sts_b64(sb + SM2_WHI + soff, hi);
            sts_b64(sb + SM2_WLO + soff, lo);
        }
    }
    __syncthreads();

    float c2 = 0.0f, c3 = 0.0f;
    if (WRITE) {
        const float maxl  = __uint_as_float(g_maxL);
        const float maxlp = __uint_as_float(g_maxLp);
        const float s = maxl / fmaxf(maxlp, EPSF);
        c2 = (1.0f - ALPHA) * s;        // multiplies D
        c3 = ALPHA - c2;                // multiplies L
    }
    float maxlp_loc = 0.0f;

    const int arow0 = wm * 64 + (lane & 15);
    const int achk = lane >> 4;
    const int brow = wn * 32 + (lane & 7);
    const int bchk = (lane >> 3) & 1;
    const int rbase0 = b0 + wm * 64 + (lane >> 2);
    const int cbase  = j0 + wn * 32 + (lane & 3) * 2;

#pragma unroll
    for (int mt = 0; mt < 4; mt++) {
        float acc[4][4];
#pragma unroll
        for (int nt = 0; nt < 4; nt++)
#pragma unroll
            for (int q = 0; q < 4; q++) acc[nt][q] = 0.0f;

#pragma unroll
        for (int ks = 0; ks < 4; ks++) {
            unsigned bhi[4][2], blo[4][2];
#pragma unroll
            for (int nt = 0; nt < 4; nt++) {
                unsigned ba = sw_addr(sb, brow + nt * 8, ks * 2 + bchk);
                ldm_x2(ba + SM2_WHI, bhi[nt]);
                ldm_x2(ba + SM2_WLO, blo[nt]);
            }
            unsigned aa = sw_addr(sb, arow0 + mt * 16, ks * 2 + achk);
            unsigned ahi[4], alo[4];
            ldm_x4(aa + SM2_THI, ahi);
#pragma unroll
            for (int nt = 0; nt < 4; nt++) {
                mma_bf16(acc[nt], ahi, bhi[nt]);
                mma_bf16(acc[nt], ahi, blo[nt]);
            }
            ldm_x4(aa + SM2_TLO, alo);
#pragma unroll
            for (int nt = 0; nt < 4; nt++)
                mma_bf16(acc[nt], alo, bhi[nt]);
        }

        // epilogue for this mt
#pragma unroll
        for (int nt = 0; nt < 4; nt++) {
            const int j = cbase + nt * 8;
#pragma unroll
            for (int h = 0; h < 2; h++) {
                const size_t b = (size_t)(rbase0 + mt * 16 + h * 8);
                float2 l = *(const float2*)(L + b * VOCAB + j);
                float dx = acc[nt][h * 2 + 0];
                float dy = acc[nt][h * 2 + 1];
                if (WRITE) {
                    float2 o = { fmaf(c2, dx, c3 * l.x), fmaf(c2, dy, c3 * l.y) };
                    *(float2*)(out + b * VOCAB + j) = o;
                } else {
                    maxlp_loc = fmaxf(maxlp_loc,
                                      fmaxf(fabsf(dx - l.x), fabsf(dy - l.y)));
                }
            }
        }
    }

    if (!WRITE) {
#pragma unroll
        for (int off = 16; off > 0; off >>= 1)
            maxlp_loc = fmaxf(maxlp_loc, __shfl_xor_sync(0xffffffffu, maxlp_loc, off));
        if (lane == 0) wred2[wid] = maxlp_loc;
        __syncthreads();
        if (tid == 0) {
            float m = wred2[0];
#pragma unroll
            for (int k = 1; k < 8; k++) m = fmaxf(m, wred2[k]);
            atomicMax(&g_maxLp, __float_as_uint(m));
        }
    }
}

// ---------------- launch ----------------
extern "C" void kernel_launch(void* const* d_in, const int* in_sizes, int n_in,
                              void* d_out, int out_size) {
    const float* L = nullptr;
    const float* W = nullptr;
    for (int i = 0; i < n_in; i++) {
        if (in_sizes[i] == BATCH * VOCAB)     L = (const float*)d_in[i];
        else if (in_sizes[i] == VOCAB * RANK) W = (const float*)d_in[i];
    }
    if (!L && n_in >= 2) L = (const float*)d_in[1];
    if (!W && n_in >= 3) W = (const float*)d_in[2];
    float* out = (float*)d_out;

    cudaFuncSetAttribute(k_gemm1, cudaFuncAttributeMaxDynamicSharedMemorySize,
                         G1_TOTAL);
    cudaFuncSetAttribute(k_pass<false>, cudaFuncAttributeMaxDynamicSharedMemorySize,
                         SM2_TOTAL);
    cudaFuncSetAttribute(k_pass<true>, cudaFuncAttributeMaxDynamicSharedMemorySize,
                         SM2_TOTAL);

    k_init<<<(BATCH * RANK) / 256, 256>>>();
    k_gemm1<<<dim3(NKC1, 2), 256, G1_TOTAL>>>(L, W);
    k_red<<<dim3((BATCH * RANK) / 256, KGRP), 256>>>();
    k_pass<false><<<dim3(VOCAB / 128, BATCH / 128), 256, SM2_TOTAL>>>(L, W, out);
    k_pass<true ><<<dim3(VOCAB / 128, BATCH / 128), 256, SM2_TOTAL>>>(L, W, out);
}

// round 15
// speedup vs baseline: 1.0156x; 1.0156x over previous
#include <cuda_runtime.h>
#include <cstdint>

#define BATCH 256
#define VOCAB 128000
#define RANK  64
#define ALPHA 0.4f
#define EPSF  1.1920928955078125e-07f   // np.finfo(float32).eps

#define KC1   256                // k-chunk per gemm1 block
#define NKC1  (VOCAB / KC1)      // 500 k-chunks
#define PART_SZ (128 * RANK)     // 8192 floats per partial

// ---------------- scratch (no allocations allowed) ----------------
__device__ float        g_Tpart[2 * NKC1 * PART_SZ];  // per-block partial T (33 MB)
__device__ float        g_T[BATCH * RANK];            // reduced T = L @ W
__device__ unsigned int g_maxL;                       // float bits of max|L|
__device__ unsigned int g_maxLp;                      // float bits of max|Lp_raw|

// ---------------- PTX helpers ----------------
typedef unsigned long long u64;

__device__ __forceinline__ unsigned smem_u32(const void* p) {
    unsigned a;
    asm("{ .reg .u64 t; cvta.to.shared.u64 t, %1; cvt.u32.u64 %0, t; }"
        : "=r"(a) : "l"(p));
    return a;
}
__device__ __forceinline__ void sts_b64(unsigned a, u64 v) {
    asm volatile("st.shared.b64 [%0], %1;" :: "r"(a), "l"(v));
}
__device__ __forceinline__ void prefetch_l2(const void* p) {
    asm volatile("prefetch.global.L2 [%0];" :: "l"(p));
}

// ldmatrix (sm_75+, valid on compute_103)
__device__ __forceinline__ void ldm_x4(unsigned addr, unsigned* r) {
    asm volatile("ldmatrix.sync.aligned.m8n8.x4.shared.b16 {%0,%1,%2,%3}, [%4];"
                 : "=r"(r[0]), "=r"(r[1]), "=r"(r[2]), "=r"(r[3]) : "r"(addr));
}
__device__ __forceinline__ void ldm_x4t(unsigned addr, unsigned* r) {
    asm volatile("ldmatrix.sync.aligned.m8n8.x4.trans.shared.b16 {%0,%1,%2,%3}, [%4];"
                 : "=r"(r[0]), "=r"(r[1]), "=r"(r[2]), "=r"(r[3]) : "r"(addr));
}
__device__ __forceinline__ void ldm_x2(unsigned addr, unsigned* r) {
    asm volatile("ldmatrix.sync.aligned.m8n8.x2.shared.b16 {%0,%1}, [%2];"
                 : "=r"(r[0]), "=r"(r[1]) : "r"(addr));
}
// bf16 mma (sm_80+, valid on compute_103)
__device__ __forceinline__ void mma_bf16(float* c, const unsigned* a, const unsigned* b) {
    asm volatile(
        "mma.sync.aligned.m16n8k16.row.col.f32.bf16.bf16.f32 "
        "{%0,%1,%2,%3}, {%4,%5,%6,%7}, {%8,%9}, {%0,%1,%2,%3};"
        : "+f"(c[0]), "+f"(c[1]), "+f"(c[2]), "+f"(c[3])
        : "r"(a[0]), "r"(a[1]), "r"(a[2]), "r"(a[3]), "r"(b[0]), "r"(b[1]));
}

// fp32 -> (hi,lo) bf16 split of a float4; each u64 = 4 packed bf16 in element order
__device__ __forceinline__ void split4(float4 v, u64& hi, u64& lo) {
    unsigned h01, h23, l01, l23;
    asm("cvt.rn.bf16x2.f32 %0, %1, %2;" : "=r"(h01) : "f"(v.y), "f"(v.x));
    asm("cvt.rn.bf16x2.f32 %0, %1, %2;" : "=r"(h23) : "f"(v.w), "f"(v.z));
    float hx = __uint_as_float(h01 << 16);
    float hy = __uint_as_float(h01 & 0xffff0000u);
    float hz = __uint_as_float(h23 << 16);
    float hw = __uint_as_float(h23 & 0xffff0000u);
    asm("cvt.rn.bf16x2.f32 %0, %1, %2;" : "=r"(l01) : "f"(v.y - hy), "f"(v.x - hx));
    asm("cvt.rn.bf16x2.f32 %0, %1, %2;" : "=r"(l23) : "f"(v.w - hw), "f"(v.z - hz));
    hi = (u64)h01 | ((u64)h23 << 32);
    lo = (u64)l01 | ((u64)l23 << 32);
}

// ---------------- K0: init g_T + maxima ----------------
__global__ void k_init() {
    int i = blockIdx.x * blockDim.x + threadIdx.x;
    if (i < BATCH * RANK) g_T[i] = 0.0f;
    if (i == 0) { g_maxL = 0u; g_maxLp = 0u; }
}

// ---------------- K1: partial T = L@W via split-bf16 mma.sync, fused max|L| ----------
// grid = (NKC1, 2 batch-halves), 256 threads (8 warps). Block tile 128 b x 64 r x 256 k.
#define G1_LHI 0
#define G1_LLO 16384
#define G1_WHI 32768
#define G1_WLO 40960
#define G1_TOTAL 49152

__global__ __launch_bounds__(256, 3) void k_gemm1(const float* __restrict__ L,
                                                  const float* __restrict__ W) {
    extern __shared__ char sm1[];
    const unsigned sb = smem_u32(sm1);
    __shared__ float wred[8];

    const int tid  = threadIdx.x;
    const int wid  = tid >> 5;
    const int lane = tid & 31;
    const int k0blk = blockIdx.x * KC1;
    const int b0    = blockIdx.y * 128;

    float acc[8][4];
#pragma unroll
    for (int nt = 0; nt < 8; nt++)
#pragma unroll
        for (int q = 0; q < 4; q++) acc[nt][q] = 0.0f;

    float maxl = 0.0f;

    for (int kt = 0; kt < KC1; kt += 64) {
        const int k0 = k0blk + kt;
        __syncthreads();
#pragma unroll
        for (int it = 0; it < 8; it++) {
            int idx = tid + it * 256;
            int row = idx >> 4;
            int kq  = idx & 15;
            float4 v = *(const float4*)(L + (size_t)(b0 + row) * VOCAB + k0 + kq * 4);
            maxl = fmaxf(maxl, fmaxf(fmaxf(fabsf(v.x), fabsf(v.y)),
                                     fmaxf(fabsf(v.z), fabsf(v.w))));
            unsigned soff = row * 128 + (((kq >> 1) ^ (row & 7)) << 4) + ((kq & 1) << 3);
            u64 hi, lo; split4(v, hi, lo);
            sts_b64(sb + G1_LHI + soff, hi);
            sts_b64(sb + G1_LLO + soff, lo);
        }
#pragma unroll
        for (int it = 0; it < 4; it++) {
            int idx = tid + it * 256;
            int krow = idx >> 4;
            int rq   = idx & 15;
            float4 v = *(const float4*)(W + (size_t)(k0 + krow) * RANK + rq * 4);
            unsigned soff = krow * 128 + (((rq >> 1) ^ (krow & 7)) << 4) + ((rq & 1) << 3);
            u64 hi, lo; split4(v, hi, lo);
            sts_b64(sb + G1_WHI + soff, hi);
            sts_b64(sb + G1_WLO + soff, lo);
        }
        __syncthreads();

#pragma unroll
        for (int ks = 0; ks < 4; ks++) {
            const int arow = wid * 16 + (lane & 15);
            const unsigned aaddr = sb + arow * 128 +
                (((ks * 2 + (lane >> 4)) ^ (arow & 7)) << 4);
            const int kloc = ks * 16 + (lane & 15);
            unsigned ahi[4], alo[4];
            unsigned bhi[4][4];
#pragma unroll
            for (int nt2 = 0; nt2 < 4; nt2++) {
                unsigned baddr = sb + kloc * 128 +
                    (((nt2 * 2 + (lane >> 4)) ^ (lane & 7)) << 4);
                ldm_x4t(baddr + G1_WHI, bhi[nt2]);
            }
            ldm_x4(aaddr + G1_LHI, ahi);
#pragma unroll
            for (int nt2 = 0; nt2 < 4; nt2++) {
                mma_bf16(acc[nt2 * 2 + 0], ahi, bhi[nt2] + 0);
                mma_bf16(acc[nt2 * 2 + 1], ahi, bhi[nt2] + 2);
            }
#pragma unroll
            for (int nt2 = 0; nt2 < 4; nt2++) {
                unsigned blo[4];
                unsigned baddr = sb + kloc * 128 +
                    (((nt2 * 2 + (lane >> 4)) ^ (lane & 7)) << 4);
                ldm_x4t(baddr + G1_WLO, blo);
                mma_bf16(acc[nt2 * 2 + 0], ahi, blo + 0);
                mma_bf16(acc[nt2 * 2 + 1], ahi, blo + 2);
            }
            ldm_x4(aaddr + G1_LLO, alo);
#pragma unroll
            for (int nt2 = 0; nt2 < 4; nt2++) {
                mma_bf16(acc[nt2 * 2 + 0], alo, bhi[nt2] + 0);
                mma_bf16(acc[nt2 * 2 + 1], alo, bhi[nt2] + 2);
            }
        }
    }

    {
        float* dst = g_Tpart + (size_t)(blockIdx.y * NKC1 + blockIdx.x) * PART_SZ;
        const int r0 = (lane & 3) * 2;
        const int rowA = wid * 16 + (lane >> 2);
#pragma unroll
        for (int nt = 0; nt < 8; nt++) {
            int c = nt * 8 + r0;
            *(float2*)(dst + rowA * RANK + c)       = make_float2(acc[nt][0], acc[nt][1]);
            *(float2*)(dst + (rowA + 8) * RANK + c) = make_float2(acc[nt][2], acc[nt][3]);
        }
    }

#pragma unroll
    for (int off = 16; off > 0; off >>= 1)
        maxl = fmaxf(maxl, __shfl_xor_sync(0xffffffffu, maxl, off));
    if (lane == 0) wred[wid] = maxl;
    __syncthreads();
    if (tid == 0) {
        float m = wred[0];
#pragma unroll
        for (int k = 1; k < 8; k++) m = fmaxf(m, wred[k]);
        atomicMax(&g_maxL, __float_as_uint(m));
    }
}

// ---------------- K1b: reduce partials -> g_T ----------------
#define KGRP 10
#define KPER (NKC1 / KGRP)       // 50
__global__ void k_red() {
    const int i = blockIdx.x * blockDim.x + threadIdx.x;
    const int b = i >> 6;
    const int r = i & 63;
    const int half = b >> 7;
    const size_t off = (size_t)(b & 127) * RANK + r;
    const size_t base = ((size_t)half * NKC1 + blockIdx.y * KPER) * PART_SZ + off;

    float s0 = 0.f, s1 = 0.f;
#pragma unroll 2
    for (int p = 0; p < KPER; p += 2) {
        s0 += g_Tpart[base + (size_t)(p + 0) * PART_SZ];
        s1 += g_Tpart[base + (size_t)(p + 1) * PART_SZ];
    }
    atomicAdd(&g_T[i], s0 + s1);
}

// ---------------- K2: two-pass split-bf16 mma.sync over D = T@W.T ----------------
// Pass A (WRITE=false): maxLp = max|D - L|, no stores.
// Pass B (WRITE=true):  out   = c2*D + (alpha - c2)*L.
// grid = (VOCAB/128, BATCH/128), 256 threads (8 warps, 2M x 4N).
// L2 prefetch of the epilogue L-tile issued at kernel start so the DRAM fetch
// overlaps staging + MMA.
#define SM2_TILE 16384
#define SM2_THI  0
#define SM2_TLO  (1 * SM2_TILE)
#define SM2_WHI  (2 * SM2_TILE)
#define SM2_WLO  (3 * SM2_TILE)
#define SM2_TOTAL (4 * SM2_TILE)      // 65536 B

__device__ __forceinline__ unsigned sw_addr(unsigned base, int row, int chunk) {
    return base + row * 128 + ((chunk ^ (row & 7)) << 4);
}

template <bool WRITE>
__global__ __launch_bounds__(256, 2) void k_pass(const float* __restrict__ L,
                                                 const float* __restrict__ W,
                                                 float* __restrict__ out) {
    extern __shared__ char sm2[];
    const unsigned sb = smem_u32(sm2);
    __shared__ float wred2[8];

    const int tid  = threadIdx.x;
    const int wid  = tid >> 5;
    const int lane = tid & 31;
    const int wm   = wid >> 2;
    const int wn   = wid & 3;
    const int j0   = blockIdx.x * 128;
    const int b0   = blockIdx.y * 128;

    // prefetch this block's 128x128 L tile into L2 (512 lines of 128 B)
#pragma unroll
    for (int pf = 0; pf < 2; pf++) {
        int idx = tid * 2 + pf;          // 0..511
        int row = idx >> 2;
        int seg = idx & 3;
        prefetch_l2(L + (size_t)(b0 + row) * VOCAB + j0 + seg * 32);
    }

#pragma unroll
    for (int it = 0; it < 8; it++) {
        int idx = tid + it * 256;
        int row = idx >> 4;
        int rq  = idx & 15;
        unsigned soff = row * 128 + (((rq >> 1) ^ (row & 7)) << 4) + ((rq & 1) << 3);
        {
            float4 v = *(const float4*)(g_T + (size_t)(b0 + row) * RANK + rq * 4);
            u64 hi, lo; split4(v, hi, lo);
            sts_b64(sb + SM2_THI + soff, hi);
            sts_b64(sb + SM2_TLO + soff, lo);
        }
        {
            float4 v = *(const float4*)(W + (size_t)(j0 + row) * RANK + rq * 4);
            u64 hi, lo; split4(v, hi, lo);
            sts_b64(sb + SM2_WHI + soff, hi);
            sts_b64(sb + SM2_WLO + soff, lo);
        }
    }
    __syncthreads();

    float acc[4][4][4];
#pragma unroll
    for (int mt = 0; mt < 4; mt++)
#pragma unroll
        for (int nt = 0; nt < 4; nt++)
#pragma unroll
            for (int q = 0; q < 4; q++) acc[mt][nt][q] = 0.0f;

    const int arow = wm * 64 + (lane & 15);
    const int achk = lane >> 4;
    const int brow = wn * 32 + (lane & 7);
    const int bchk = (lane >> 3) & 1;

#pragma unroll
    for (int ks = 0; ks < 4; ks++) {
        unsigned bhi[4][2], blo[4][2];
#pragma unroll
        for (int nt = 0; nt < 4; nt++) {
            unsigned ba = sw_addr(sb, brow + nt * 8, ks * 2 + bchk);
            ldm_x2(ba + SM2_WHI, bhi[nt]);
            ldm_x2(ba + SM2_WLO, blo[nt]);
        }
#pragma unroll
        for (int mt = 0; mt < 4; mt++) {
            unsigned aa = sw_addr(sb, arow + mt * 16, ks * 2 + achk);
            unsigned ahi[4], alo[4];
            ldm_x4(aa + SM2_THI, ahi);
#pragma unroll
            for (int nt = 0; nt < 4; nt++) {
                mma_bf16(acc[mt][nt], ahi, bhi[nt]);
                mma_bf16(acc[mt][nt], ahi, blo[nt]);
            }
            ldm_x4(aa + SM2_TLO, alo);
#pragma unroll
            for (int nt = 0; nt < 4; nt++)
                mma_bf16(acc[mt][nt], alo, bhi[nt]);
        }
    }

    // epilogue
    float c2 = 0.0f, c3 = 0.0f;
    if (WRITE) {
        const float maxl  = __uint_as_float(g_maxL);
        const float maxlp = __uint_as_float(g_maxLp);
        const float s = maxl / fmaxf(maxlp, EPSF);
        c2 = (1.0f - ALPHA) * s;        // multiplies D
        c3 = ALPHA - c2;                // multiplies L
    }
    float maxlp_loc = 0.0f;
    const int rbase = b0 + wm * 64 + (lane >> 2);
    const int cbase = j0 + wn * 32 + (lane & 3) * 2;
#pragma unroll
    for (int mt = 0; mt < 4; mt++) {
#pragma unroll
        for (int nt = 0; nt < 4; nt++) {
            const int j = cbase + nt * 8;
#pragma unroll
            for (int h = 0; h < 2; h++) {
                const size_t b = (size_t)(rbase + mt * 16 + h * 8);
                float2 l = *(const float2*)(L + b * VOCAB + j);
                float dx = acc[mt][nt][h * 2 + 0];
                float dy = acc[mt][nt][h * 2 + 1];
                if (WRITE) {
                    float2 o = { fmaf(c2, dx, c3 * l.x), fmaf(c2, dy, c3 * l.y) };
                    *(float2*)(out + b * VOCAB + j) = o;
                } else {
                    maxlp_loc = fmaxf(maxlp_loc,
                                      fmaxf(fabsf(dx - l.x), fabsf(dy - l.y)));
                }
            }
        }
    }

    if (!WRITE) {
#pragma unroll
        for (int off = 16; off > 0; off >>= 1)
            maxlp_loc = fmaxf(maxlp_loc, __shfl_xor_sync(0xffffffffu, maxlp_loc, off));
        if (lane == 0) wred2[wid] = maxlp_loc;
        __syncthreads();
        if (tid == 0) {
            float m = wred2[0];
#pragma unroll
            for (int k = 1; k < 8; k++) m = fmaxf(m, wred2[k]);
            atomicMax(&g_maxLp, __float_as_uint(m));
        }
    }
}

// ---------------- launch ----------------
extern "C" void kernel_launch(void* const* d_in, const int* in_sizes, int n_in,
                              void* d_out, int out_size) {
    const float* L = nullptr;
    const float* W = nullptr;
    for (int i = 0; i < n_in; i++) {
        if (in_sizes[i] == BATCH * VOCAB)     L = (const float*)d_in[i];
        else if (in_sizes[i] == VOCAB * RANK) W = (const float*)d_in[i];
    }
    if (!L && n_in >= 2) L = (const float*)d_in[1];
    if (!W && n_in >= 3) W = (const float*)d_in[2];
    float* out = (float*)d_out;

    cudaFuncSetAttribute(k_gemm1, cudaFuncAttributeMaxDynamicSharedMemorySize,
                         G1_TOTAL);
    cudaFuncSetAttribute(k_pass<false>, cudaFuncAttributeMaxDynamicSharedMemorySize,
                         SM2_TOTAL);
    cudaFuncSetAttribute(k_pass<true>, cudaFuncAttributeMaxDynamicSharedMemorySize,
                         SM2_TOTAL);

    k_init<<<(BATCH * RANK) / 256, 256>>>();
    k_gemm1<<<dim3(NKC1, 2), 256, G1_TOTAL>>>(L, W);
    k_red<<<dim3((BATCH * RANK) / 256, KGRP), 256>>>();
    k_pass<false><<<dim3(VOCAB / 128, BATCH / 128), 256, SM2_TOTAL>>>(L, W, out);
    k_pass<true ><<<dim3(VOCAB / 128, BATCH / 128), 256, SM2_TOTAL>>>(L, W, out);
}

// round 16
// speedup vs baseline: 1.2332x; 1.2142x over previous
#include <cuda_runtime.h>
#include <cstdint>

#define BATCH 256
#define VOCAB 128000
#define RANK  64
#define ALPHA 0.4f
#define EPSF  1.1920928955078125e-07f   // np.finfo(float32).eps

#define KC1   256                // k-chunk per gemm1 block
#define NKC1  (VOCAB / KC1)      // 500 k-chunks
#define PART_SZ (128 * RANK)     // 8192 floats per partial

// ---------------- scratch (no allocations allowed) ----------------
__device__ float        g_Tpart[2 * NKC1 * PART_SZ];  // per-block partial T (33 MB)
__device__ float        g_T[BATCH * RANK];            // reduced T = L @ W
__device__ unsigned int g_maxL;                       // float bits of max|L|
__device__ unsigned int g_maxLp;                      // float bits of max|Lp_raw|

// ---------------- PTX helpers ----------------
typedef unsigned long long u64;

__device__ __forceinline__ unsigned smem_u32(const void* p) {
    unsigned a;
    asm("{ .reg .u64 t; cvta.to.shared.u64 t, %1; cvt.u32.u64 %0, t; }"
        : "=r"(a) : "l"(p));
    return a;
}
__device__ __forceinline__ void sts_b64(unsigned a, u64 v) {
    asm volatile("st.shared.b64 [%0], %1;" :: "r"(a), "l"(v));
}
__device__ __forceinline__ void cp_async16(unsigned saddr, const void* gptr) {
    asm volatile("cp.async.cg.shared.global [%0], [%1], 16;"
                 :: "r"(saddr), "l"(gptr));
}
#define CP_COMMIT() asm volatile("cp.async.commit_group;" ::: "memory")
#define CP_WAIT0()  asm volatile("cp.async.wait_group 0;" ::: "memory")

// ldmatrix (sm_75+, valid on compute_103)
__device__ __forceinline__ void ldm_x4(unsigned addr, unsigned* r) {
    asm volatile("ldmatrix.sync.aligned.m8n8.x4.shared.b16 {%0,%1,%2,%3}, [%4];"
                 : "=r"(r[0]), "=r"(r[1]), "=r"(r[2]), "=r"(r[3]) : "r"(addr));
}
__device__ __forceinline__ void ldm_x4t(unsigned addr, unsigned* r) {
    asm volatile("ldmatrix.sync.aligned.m8n8.x4.trans.shared.b16 {%0,%1,%2,%3}, [%4];"
                 : "=r"(r[0]), "=r"(r[1]), "=r"(r[2]), "=r"(r[3]) : "r"(addr));
}
__device__ __forceinline__ void ldm_x2(unsigned addr, unsigned* r) {
    asm volatile("ldmatrix.sync.aligned.m8n8.x2.shared.b16 {%0,%1}, [%2];"
                 : "=r"(r[0]), "=r"(r[1]) : "r"(addr));
}
// bf16 mma (sm_80+, valid on compute_103)
__device__ __forceinline__ void mma_bf16(float* c, const unsigned* a, const unsigned* b) {
    asm volatile(
        "mma.sync.aligned.m16n8k16.row.col.f32.bf16.bf16.f32 "
        "{%0,%1,%2,%3}, {%4,%5,%6,%7}, {%8,%9}, {%0,%1,%2,%3};"
        : "+f"(c[0]), "+f"(c[1]), "+f"(c[2]), "+f"(c[3])
        : "r"(a[0]), "r"(a[1]), "r"(a[2]), "r"(a[3]), "r"(b[0]), "r"(b[1]));
}

// fp32 -> (hi,lo) bf16 split of a float4; each u64 = 4 packed bf16 in element order
__device__ __forceinline__ void split4(float4 v, u64& hi, u64& lo) {
    unsigned h01, h23, l01, l23;
    asm("cvt.rn.bf16x2.f32 %0, %1, %2;" : "=r"(h01) : "f"(v.y), "f"(v.x));
    asm("cvt.rn.bf16x2.f32 %0, %1, %2;" : "=r"(h23) : "f"(v.w), "f"(v.z));
    float hx = __uint_as_float(h01 << 16);
    float hy = __uint_as_float(h01 & 0xffff0000u);
    float hz = __uint_as_float(h23 << 16);
    float hw = __uint_as_float(h23 & 0xffff0000u);
    asm("cvt.rn.bf16x2.f32 %0, %1, %2;" : "=r"(l01) : "f"(v.y - hy), "f"(v.x - hx));
    asm("cvt.rn.bf16x2.f32 %0, %1, %2;" : "=r"(l23) : "f"(v.w - hw), "f"(v.z - hz));
    hi = (u64)h01 | ((u64)h23 << 32);
    lo = (u64)l01 | ((u64)l23 << 32);
}

// ---------------- K0: init g_T + maxima ----------------
__global__ void k_init() {
    int i = blockIdx.x * blockDim.x + threadIdx.x;
    if (i < BATCH * RANK) g_T[i] = 0.0f;
    if (i == 0) { g_maxL = 0u; g_maxLp = 0u; }
}

// ---------------- K1: partial T = L@W via split-bf16 mma.sync, fused max|L| ----------
// grid = (NKC1, 2 batch-halves), 256 threads (8 warps). Block tile 128 b x 64 r x 256 k.
// cp.async pipeline: chunk kt+1 streams into a fp32 smem buffer while chunk kt's
// MMA runs; the split phase reads fp32 from smem (no DRAM wait on critical path).
#define G1_LHI 0
#define G1_LLO 16384
#define G1_WHI 32768
#define G1_WLO 40960
#define G1_FL  49152                 // fp32 L chunk buffer: 2048 float4 = 32 KB
#define G1_FW  (49152 + 32768)       // fp32 W chunk buffer: 1024 float4 = 16 KB
#define G1_TOTAL (49152 + 49152)     // 98304 B

__global__ __launch_bounds__(256, 2) void k_gemm1(const float* __restrict__ L,
                                                  const float* __restrict__ W) {
    extern __shared__ char sm1[];
    const unsigned sb = smem_u32(sm1);
    __shared__ float wred[8];

    const int tid  = threadIdx.x;
    const int wid  = tid >> 5;
    const int lane = tid & 31;
    const int k0blk = blockIdx.x * KC1;
    const int b0    = blockIdx.y * 128;

    float acc[8][4];
#pragma unroll
    for (int nt = 0; nt < 8; nt++)
#pragma unroll
        for (int q = 0; q < 4; q++) acc[nt][q] = 0.0f;

    float maxl = 0.0f;

    // prologue: stream chunk 0 into fp32 buffer
#pragma unroll
    for (int it = 0; it < 8; it++) {
        int idx = tid + it * 256;
        int row = idx >> 4;
        int kq  = idx & 15;
        cp_async16(sb + G1_FL + idx * 16,
                   L + (size_t)(b0 + row) * VOCAB + k0blk + kq * 4);
    }
#pragma unroll
    for (int it = 0; it < 4; it++) {
        int idx = tid + it * 256;
        int krow = idx >> 4;
        int rq   = idx & 15;
        cp_async16(sb + G1_FW + idx * 16,
                   W + (size_t)(k0blk + krow) * RANK + rq * 4);
    }
    CP_COMMIT();
    CP_WAIT0();
    __syncthreads();

    for (int kt = 0; kt < KC1; kt += 64) {
        // split fp32 buffer -> bf16 hi/lo tiles; fused abs-max
#pragma unroll
        for (int it = 0; it < 8; it++) {
            int idx = tid + it * 256;
            int row = idx >> 4;
            int kq  = idx & 15;
            float4 v = *(const float4*)(sm1 + G1_FL + idx * 16);
            maxl = fmaxf(maxl, fmaxf(fmaxf(fabsf(v.x), fabsf(v.y)),
                                     fmaxf(fabsf(v.z), fabsf(v.w))));
            unsigned soff = row * 128 + (((kq >> 1) ^ (row & 7)) << 4) + ((kq & 1) << 3);
            u64 hi, lo; split4(v, hi, lo);
            sts_b64(sb + G1_LHI + soff, hi);
            sts_b64(sb + G1_LLO + soff, lo);
        }
#pragma unroll
        for (int it = 0; it < 4; it++) {
            int idx = tid + it * 256;
            int krow = idx >> 4;
            int rq   = idx & 15;
            float4 v = *(const float4*)(sm1 + G1_FW + idx * 16);
            unsigned soff = krow * 128 + (((rq >> 1) ^ (krow & 7)) << 4) + ((rq & 1) << 3);
            u64 hi, lo; split4(v, hi, lo);
            sts_b64(sb + G1_WHI + soff, hi);
            sts_b64(sb + G1_WLO + soff, lo);
        }
        __syncthreads();   // tiles ready; fp32 buffer fully consumed

        // stream next chunk into fp32 buffer (overlaps MMA below)
        if (kt + 64 < KC1) {
            const int kn = k0blk + kt + 64;
#pragma unroll
            for (int it = 0; it < 8; it++) {
                int idx = tid + it * 256;
                int row = idx >> 4;
                int kq  = idx & 15;
                cp_async16(sb + G1_FL + idx * 16,
                           L + (size_t)(b0 + row) * VOCAB + kn + kq * 4);
            }
#pragma unroll
            for (int it = 0; it < 4; it++) {
                int idx = tid + it * 256;
                int krow = idx >> 4;
                int rq   = idx & 15;
                cp_async16(sb + G1_FW + idx * 16,
                           W + (size_t)(kn + krow) * RANK + rq * 4);
            }
            CP_COMMIT();
        }

        // MMA on staged tiles
#pragma unroll
        for (int ks = 0; ks < 4; ks++) {
            const int arow = wid * 16 + (lane & 15);
            const unsigned aaddr = sb + arow * 128 +
                (((ks * 2 + (lane >> 4)) ^ (arow & 7)) << 4);
            const int kloc = ks * 16 + (lane & 15);
            unsigned ahi[4], alo[4];
            unsigned bhi[4][4];
#pragma unroll
            for (int nt2 = 0; nt2 < 4; nt2++) {
                unsigned baddr = sb + kloc * 128 +
                    (((nt2 * 2 + (lane >> 4)) ^ (lane & 7)) << 4);
                ldm_x4t(baddr + G1_WHI, bhi[nt2]);
            }
            ldm_x4(aaddr + G1_LHI, ahi);
#pragma unroll
            for (int nt2 = 0; nt2 < 4; nt2++) {
                mma_bf16(acc[nt2 * 2 + 0], ahi, bhi[nt2] + 0);
                mma_bf16(acc[nt2 * 2 + 1], ahi, bhi[nt2] + 2);
            }
#pragma unroll
            for (int nt2 = 0; nt2 < 4; nt2++) {
                unsigned blo[4];
                unsigned baddr = sb + kloc * 128 +
                    (((nt2 * 2 + (lane >> 4)) ^ (lane & 7)) << 4);
                ldm_x4t(baddr + G1_WLO, blo);
                mma_bf16(acc[nt2 * 2 + 0], ahi, blo + 0);
                mma_bf16(acc[nt2 * 2 + 1], ahi, blo + 2);
            }
            ldm_x4(aaddr + G1_LLO, alo);
#pragma unroll
            for (int nt2 = 0; nt2 < 4; nt2++) {
                mma_bf16(acc[nt2 * 2 + 0], alo, bhi[nt2] + 0);
                mma_bf16(acc[nt2 * 2 + 1], alo, bhi[nt2] + 2);
            }
        }
        CP_WAIT0();
        __syncthreads();   // MMA done reading tiles; next chunk's fp32 ready
    }

    {
        float* dst = g_Tpart + (size_t)(blockIdx.y * NKC1 + blockIdx.x) * PART_SZ;
        const int r0 = (lane & 3) * 2;
        const int rowA = wid * 16 + (lane >> 2);
#pragma unroll
        for (int nt = 0; nt < 8; nt++) {
            int c = nt * 8 + r0;
            *(float2*)(dst + rowA * RANK + c)       = make_float2(acc[nt][0], acc[nt][1]);
            *(float2*)(dst + (rowA + 8) * RANK + c) = make_float2(acc[nt][2], acc[nt][3]);
        }
    }

#pragma unroll
    for (int off = 16; off > 0; off >>= 1)
        maxl = fmaxf(maxl, __shfl_xor_sync(0xffffffffu, maxl, off));
    if (lane == 0) wred[wid] = maxl;
    __syncthreads();
    if (tid == 0) {
        float m = wred[0];
#pragma unroll
        for (int k = 1; k < 8; k++) m = fmaxf(m, wred[k]);
        atomicMax(&g_maxL, __float_as_uint(m));
    }
}

// ---------------- K1b: reduce partials -> g_T ----------------
#define KGRP 10
#define KPER (NKC1 / KGRP)       // 50
__global__ void k_red() {
    const int i = blockIdx.x * blockDim.x + threadIdx.x;
    const int b = i >> 6;
    const int r = i & 63;
    const int half = b >> 7;
    const size_t off = (size_t)(b & 127) * RANK + r;
    const size_t base = ((size_t)half * NKC1 + blockIdx.y * KPER) * PART_SZ + off;

    float s0 = 0.f, s1 = 0.f;
#pragma unroll 2
    for (int p = 0; p < KPER; p += 2) {
        s0 += g_Tpart[base + (size_t)(p + 0) * PART_SZ];
        s1 += g_Tpart[base + (size_t)(p + 1) * PART_SZ];
    }
    atomicAdd(&g_T[i], s0 + s1);
}

// ---------------- K2: two-pass split-bf16 mma.sync over D = T@W.T ----------------
// Pass A (WRITE=false): maxLp = max|D - L|, no stores.
// Pass B (WRITE=true):  out   = c2*D + (alpha - c2)*L.
// grid = (VOCAB/128, BATCH/128), 256 threads (8 warps, 2M x 4N).
#define SM2_TILE 16384
#define SM2_THI  0
#define SM2_TLO  (1 * SM2_TILE)
#define SM2_WHI  (2 * SM2_TILE)
#define SM2_WLO  (3 * SM2_TILE)
#define SM2_TOTAL (4 * SM2_TILE)      // 65536 B

__device__ __forceinline__ unsigned sw_addr(unsigned base, int row, int chunk) {
    return base + row * 128 + ((chunk ^ (row & 7)) << 4);
}

template <bool WRITE>
__global__ __launch_bounds__(256, 2) void k_pass(const float* __restrict__ L,
                                                 const float* __restrict__ W,
                                                 float* __restrict__ out) {
    extern __shared__ char sm2[];
    const unsigned sb = smem_u32(sm2);
    __shared__ float wred2[8];

    const int tid  = threadIdx.x;
    const int wid  = tid >> 5;
    const int lane = tid & 31;
    const int wm   = wid >> 2;
    const int wn   = wid & 3;
    const int j0   = blockIdx.x * 128;
    const int b0   = blockIdx.y * 128;

#pragma unroll
    for (int it = 0; it < 8; it++) {
        int idx = tid + it * 256;
        int row = idx >> 4;
        int rq  = idx & 15;
        unsigned soff = row * 128 + (((rq >> 1) ^ (row & 7)) << 4) + ((rq & 1) << 3);
        {
            float4 v = *(const float4*)(g_T + (size_t)(b0 + row) * RANK + rq * 4);
            u64 hi, lo; split4(v, hi, lo);
            sts_b64(sb + SM2_THI + soff, hi);
            sts_b64(sb + SM2_TLO + soff, lo);
        }
        {
            float4 v = *(const float4*)(W + (size_t)(j0 + row) * RANK + rq * 4);
            u64 hi, lo; split4(v, hi, lo);
            sts_b64(sb + SM2_WHI + soff, hi);
            sts_b64(sb + SM2_WLO + soff, lo);
        }
    }
    __syncthreads();

    float acc[4][4][4];
#pragma unroll
    for (int mt = 0; mt < 4; mt++)
#pragma unroll
        for (int nt = 0; nt < 4; nt++)
#pragma unroll
            for (int q = 0; q < 4; q++) acc[mt][nt][q] = 0.0f;

    const int arow = wm * 64 + (lane & 15);
    const int achk = lane >> 4;
    const int brow = wn * 32 + (lane & 7);
    const int bchk = (lane >> 3) & 1;

#pragma unroll
    for (int ks = 0; ks < 4; ks++) {
        unsigned bhi[4][2], blo[4][2];
#pragma unroll
        for (int nt = 0; nt < 4; nt++) {
            unsigned ba = sw_addr(sb, brow + nt * 8, ks * 2 + bchk);
            ldm_x2(ba + SM2_WHI, bhi[nt]);
            ldm_x2(ba + SM2_WLO, blo[nt]);
        }
#pragma unroll
        for (int mt = 0; mt < 4; mt++) {
            unsigned aa = sw_addr(sb, arow + mt * 16, ks * 2 + achk);
            unsigned ahi[4], alo[4];
            ldm_x4(aa + SM2_THI, ahi);
#pragma unroll
            for (int nt = 0; nt < 4; nt++) {
                mma_bf16(acc[mt][nt], ahi, bhi[nt]);
                mma_bf16(acc[mt][nt], ahi, blo[nt]);
            }
            ldm_x4(aa + SM2_TLO, alo);
#pragma unroll
            for (int nt = 0; nt < 4; nt++)
                mma_bf16(acc[mt][nt], alo, bhi[nt]);
        }
    }

    // epilogue
    float c2 = 0.0f, c3 = 0.0f;
    if (WRITE) {
        const float maxl  = __uint_as_float(g_maxL);
        const float maxlp = __uint_as_float(g_maxLp);
        const float s = maxl / fmaxf(maxlp, EPSF);
        c2 = (1.0f - ALPHA) * s;        // multiplies D
        c3 = ALPHA - c2;                // multiplies L
    }
    float maxlp_loc = 0.0f;
    const int rbase = b0 + wm * 64 + (lane >> 2);
    const int cbase = j0 + wn * 32 + (lane & 3) * 2;
#pragma unroll
    for (int mt = 0; mt < 4; mt++) {
#pragma unroll
        for (int nt = 0; nt < 4; nt++) {
            const int j = cbase + nt * 8;
#pragma unroll
            for (int h = 0; h < 2; h++) {
                const size_t b = (size_t)(rbase + mt * 16 + h * 8);
                float2 l = *(const float2*)(L + b * VOCAB + j);
                float dx = acc[mt][nt][h * 2 + 0];
                float dy = acc[mt][nt][h * 2 + 1];
                if (WRITE) {
                    float2 o = { fmaf(c2, dx, c3 * l.x), fmaf(c2, dy, c3 * l.y) };
                    *(float2*)(out + b * VOCAB + j) = o;
                } else {
                    maxlp_loc = fmaxf(maxlp_loc,
                                      fmaxf(fabsf(dx - l.x), fabsf(dy - l.y)));
                }
            }
        }
    }

    if (!WRITE) {
#pragma unroll
        for (int off = 16; off > 0; off >>= 1)
            maxlp_loc = fmaxf(maxlp_loc, __shfl_xor_sync(0xffffffffu, maxlp_loc, off));
        if (lane == 0) wred2[wid] = maxlp_loc;
        __syncthreads();
        if (tid == 0) {
            float m = wred2[0];
#pragma unroll
            for (int k = 1; k < 8; k++) m = fmaxf(m, wred2[k]);
            atomicMax(&g_maxLp, __float_as_uint(m));
        }
    }
}

// ---------------- launch ----------------
extern "C" void kernel_launch(void* const* d_in, const int* in_sizes, int n_in,
                              void* d_out, int out_size) {
    const float* L = nullptr;
    const float* W = nullptr;
    for (int i = 0; i < n_in; i++) {
        if (in_sizes[i] == BATCH * VOCAB)     L = (const float*)d_in[i];
        else if (in_sizes[i] == VOCAB * RANK) W = (const float*)d_in[i];
    }
    if (!L && n_in >= 2) L = (const float*)d_in[1];
    if (!W && n_in >= 3) W = (const float*)d_in[2];
    float* out = (float*)d_out;

    cudaFuncSetAttribute(k_gemm1, cudaFuncAttributeMaxDynamicSharedMemorySize,
                         G1_TOTAL);
    cudaFuncSetAttribute(k_pass<false>, cudaFuncAttributeMaxDynamicSharedMemorySize,
                         SM2_TOTAL);
    cudaFuncSetAttribute(k_pass<true>, cudaFuncAttributeMaxDynamicSharedMemorySize,
                         SM2_TOTAL);

    k_init<<<(BATCH * RANK) / 256, 256>>>();
    k_gemm1<<<dim3(NKC1, 2), 256, G1_TOTAL>>>(L, W);
    k_red<<<dim3((BATCH * RANK) / 256, KGRP), 256>>>();
    k_pass<false><<<dim3(VOCAB / 128, BATCH / 128), 256, SM2_TOTAL>>>(L, W, out);
    k_pass<true ><<<dim3(VOCAB / 128, BATCH / 128), 256, SM2_TOTAL>>>(L, W, out);
}